// round 16
// baseline (speedup 1.0000x reference)
#include <cuda_runtime.h>
#include <cuda_fp16.h>
#include <math.h>
#include <stdint.h>

#define BB 8
#define SS 512
#define HID 768
#define NH 12
#define DHD 64
#define INTER 3072
#define LAY 4
#define TOK (BB*SS)
#define QKVN (3*HID)
#define BNH (BB*NH)
#define HID2 (HID/2)
#define QKVN2 (QKVN/2)
#define INTER2 (INTER/2)
#define SS2 (SS/2)

// ---------------------------------------------------------------------------
// Scratch (all packed-fp16x2)
// ---------------------------------------------------------------------------
__device__ float g_kb [LAY*NH*SS];

__device__ uint32_t g_h_hi [TOK*HID2];
__device__ uint32_t g_y_hi [TOK*HID2];
__device__ uint32_t g_qkv_hi[TOK*QKVN2];
__device__ uint32_t g_at_hi[TOK*HID2];
__device__ uint32_t g_ao_hi[TOK*HID2];
__device__ uint32_t g_x_hi [(size_t)TOK*INTER2];

__device__ uint32_t g_wqkv_hi[LAY*QKVN*HID/2];
__device__ uint32_t g_wao_hi [LAY*HID*HID/2];
__device__ uint32_t g_wglu_hi[(size_t)LAY*2*INTER*HID/2];
__device__ uint32_t g_wwo_hi [(size_t)LAY*HID*INTER/2];

// ---------------------------------------------------------------------------
// Helpers
// ---------------------------------------------------------------------------
__device__ __forceinline__ uint32_t packh(float f0, float f1) {
    __half h0 = __float2half_rn(f0), h1 = __float2half_rn(f1);
    return ((uint32_t)__half_as_ushort(h1) << 16) | (uint32_t)__half_as_ushort(h0);
}

__device__ __forceinline__ void unpackh(uint32_t hi, float& f0, float& f1) {
    f0 = __half2float(__ushort_as_half((unsigned short)(hi & 0xffff)));
    f1 = __half2float(__ushort_as_half((unsigned short)(hi >> 16)));
}

__device__ __forceinline__ void mma16(float* c, const uint32_t* a, const uint32_t* b) {
    asm volatile(
        "mma.sync.aligned.m16n8k16.row.col.f32.f16.f16.f32 "
        "{%0,%1,%2,%3}, {%4,%5,%6,%7}, {%8,%9}, {%0,%1,%2,%3};"
        : "+f"(c[0]), "+f"(c[1]), "+f"(c[2]), "+f"(c[3])
        : "r"(a[0]), "r"(a[1]), "r"(a[2]), "r"(a[3]), "r"(b[0]), "r"(b[1]));
}

__device__ __forceinline__ void ldsm4(uint32_t* r, uint32_t saddr) {
    asm volatile("ldmatrix.sync.aligned.m8n8.x4.shared.b16 {%0,%1,%2,%3}, [%4];"
        : "=r"(r[0]), "=r"(r[1]), "=r"(r[2]), "=r"(r[3]) : "r"(saddr));
}

__device__ __forceinline__ void ldsm4t(uint32_t* r, uint32_t saddr) {
    asm volatile("ldmatrix.sync.aligned.m8n8.x4.trans.shared.b16 {%0,%1,%2,%3}, [%4];"
        : "=r"(r[0]), "=r"(r[1]), "=r"(r[2]), "=r"(r[3]) : "r"(saddr));
}

__device__ __forceinline__ void cp16s(uint32_t saddr, const void* g) {
    asm volatile("cp.async.ca.shared.global [%0], [%1], 16;" :: "r"(saddr), "l"(g));
}

__device__ __forceinline__ void sts32(uint32_t saddr, uint32_t v) {
    asm volatile("st.shared.u32 [%0], %1;" :: "r"(saddr), "r"(v) : "memory");
}

__device__ __forceinline__ int swz(int row, int ch) {
    return row * 64 + ((ch ^ ((row >> 1) & 3)) << 4);
}

// ---------------------------------------------------------------------------
// FP16 single-pass mainloop (proven R14: BK=32, 3-stage cp.async)
// ---------------------------------------------------------------------------
template<int IT, int JT, int WM, int WN, int BROWS>
__device__ __forceinline__ void mainloop(
    const uint32_t* __restrict__ Ahi, int lda2,
    const uint32_t* __restrict__ Bhi, int ldb2,
    int m0, int n0, int K, float (*c)[JT][4], char* smptr)
{
    constexpr int ASZ = 128 * 64;
    constexpr int BSZ = BROWS * 64;
    constexpr int STG = ASZ + BSZ;
    constexpr int BITER = (BROWS * 4) / 256;
    const int t = threadIdx.x, lane = t & 31, wid = t >> 5;
    const int wm = wid / WN, wn = wid % WN;
    const uint32_t sbase = (uint32_t)__cvta_generic_to_shared(smptr);
    const int KT = K >> 5;

    auto prefetch = [&](int st, int k0) {
        int kc = k0 >> 1;
        uint32_t s0 = sbase + st * STG;
        #pragma unroll
        for (int it2 = 0; it2 < 2; it2++) {
            int idx = t + it2 * 256; int row = idx >> 2, ch = idx & 3;
            cp16s(s0 + swz(row, ch), Ahi + (size_t)(m0 + row) * lda2 + kc + ch * 4);
        }
        #pragma unroll
        for (int it2 = 0; it2 < BITER; it2++) {
            int idx = t + it2 * 256; int row = idx >> 2, ch = idx & 3;
            cp16s(s0 + ASZ + swz(row, ch), Bhi + (size_t)(n0 + row) * ldb2 + kc + ch * 4);
        }
        asm volatile("cp.async.commit_group;");
    };

    prefetch(0, 0);
    if (KT > 1) prefetch(1, 32);

    for (int kt = 0; kt < KT; kt++) {
        int st = kt % 3;
        if (kt + 2 < KT)      { prefetch((kt + 2) % 3, (kt + 2) * 32);
                                asm volatile("cp.async.wait_group 2;"); }
        else if (kt + 1 < KT) { asm volatile("cp.async.wait_group 1;"); }
        else                  { asm volatile("cp.async.wait_group 0;"); }
        __syncthreads();

        uint32_t aH = sbase + st * STG;
        uint32_t bH = aH + ASZ;

        #pragma unroll
        for (int s = 0; s < 2; s++) {
            const int arow = wm * IT * 16 + (lane & 15);
            const int ach  = s * 2 + (lane >> 4);
            const int brow = wn * JT * 8 + (lane & 7) + ((lane >> 4) << 3);
            const int bch  = s * 2 + ((lane >> 3) & 1);

            uint32_t ah[IT][4], bh_[JT][2];
            #pragma unroll
            for (int i = 0; i < IT; i++)
                ldsm4(ah[i], aH + swz(arow + i * 16, ach));
            #pragma unroll
            for (int jp = 0; jp < JT / 2; jp++) {
                uint32_t rg[4];
                ldsm4(rg, bH + swz(brow + jp * 16, bch));
                bh_[jp*2][0] = rg[0]; bh_[jp*2][1] = rg[1];
                bh_[jp*2+1][0] = rg[2]; bh_[jp*2+1][1] = rg[3];
            }
            #pragma unroll
            for (int i = 0; i < IT; i++)
                #pragma unroll
                for (int j = 0; j < JT; j++)
                    mma16(c[i][j], ah[i], bh_[j]);
        }
        __syncthreads();
    }
}

// ---------------------------------------------------------------------------
// Generic GEMM (128x128 tile, 2 CTAs/SM)
// ---------------------------------------------------------------------------
__global__ __launch_bounds__(256, 2)
void gemm_h(const uint32_t* __restrict__ Ahi,
            const uint32_t* __restrict__ Whi,
            const float* __restrict__ bias, const uint32_t* __restrict__ resHi,
            const float* __restrict__ mask,
            uint32_t* __restrict__ outHi, int M, int N, int K)
{
    extern __shared__ char smv[];
    float c[4][4][4] = {};
    const int m0 = blockIdx.y * 128, n0 = blockIdx.x * 128;
    mainloop<4,4,2,4,128>(Ahi, K/2, Whi, K/2, m0, n0, K, c, smv);

    const int t = threadIdx.x, lane = t & 31, wid = t >> 5;
    const int gid = lane >> 2, tig = lane & 3, wm = wid >> 2, wn = wid & 3;
    const int N2 = N >> 1;
    #pragma unroll
    for (int i = 0; i < 4; i++) {
        #pragma unroll
        for (int rr = 0; rr < 2; rr++) {
            int m = m0 + wm*64 + i*16 + gid + rr*8;
            float mm = mask ? mask[m] : 1.f;
            #pragma unroll
            for (int j = 0; j < 4; j++) {
                int n = n0 + wn*32 + j*8 + tig*2;
                float v0 = c[i][j][rr*2 + 0], v1 = c[i][j][rr*2 + 1];
                if (bias) { v0 += bias[n]; v1 += bias[n+1]; }
                if (resHi) {
                    float r0, r1; unpackh(resHi[(size_t)m*N2 + (n>>1)], r0, r1);
                    v0 += r0; v1 += r1;
                }
                outHi[(size_t)m*N2 + (n>>1)] = packh(v0 * mm, v1 * mm);
            }
        }
    }
}

// ---------------------------------------------------------------------------
// Narrow GEMM (128x64 tile, 2 CTAs/SM) — for N=768 GEMMs: doubles grid to
// fill resident-CTA slots. Per-element arithmetic identical to gemm_h.
// ---------------------------------------------------------------------------
__global__ __launch_bounds__(256, 2)
void gemm_h64(const uint32_t* __restrict__ Ahi,
              const uint32_t* __restrict__ Whi,
              const float* __restrict__ bias, const uint32_t* __restrict__ resHi,
              const float* __restrict__ mask,
              uint32_t* __restrict__ outHi, int M, int N, int K)
{
    extern __shared__ char smv[];
    float c[4][2][4] = {};
    const int m0 = blockIdx.y * 128, n0 = blockIdx.x * 64;
    mainloop<4,2,2,4,64>(Ahi, K/2, Whi, K/2, m0, n0, K, c, smv);

    const int t = threadIdx.x, lane = t & 31, wid = t >> 5;
    const int gid = lane >> 2, tig = lane & 3, wm = wid >> 2, wn = wid & 3;
    const int N2 = N >> 1;
    #pragma unroll
    for (int i = 0; i < 4; i++) {
        #pragma unroll
        for (int rr = 0; rr < 2; rr++) {
            int m = m0 + wm*64 + i*16 + gid + rr*8;
            float mm = mask ? mask[m] : 1.f;
            #pragma unroll
            for (int j = 0; j < 2; j++) {
                int n = n0 + wn*16 + j*8 + tig*2;
                float v0 = c[i][j][rr*2 + 0], v1 = c[i][j][rr*2 + 1];
                if (bias) { v0 += bias[n]; v1 += bias[n+1]; }
                if (resHi) {
                    float r0, r1; unpackh(resHi[(size_t)m*N2 + (n>>1)], r0, r1);
                    v0 += r0; v1 += r1;
                }
                outHi[(size_t)m*N2 + (n>>1)] = packh(v0 * mm, v1 * mm);
            }
        }
    }
}

// ---------------------------------------------------------------------------
// GLU GEMM (128x128): interleaved weights; epilogue x = gelu(gate)*up
// ---------------------------------------------------------------------------
__global__ __launch_bounds__(256, 2)
void gemm_glu(const uint32_t* __restrict__ Ahi,
              const uint32_t* __restrict__ Whi,
              uint32_t* __restrict__ xhi, int K)
{
    extern __shared__ char smv[];
    float c[4][4][4] = {};
    const int m0 = blockIdx.y * 128, n0 = blockIdx.x * 128;
    mainloop<4,4,2,4,128>(Ahi, K/2, Whi, K/2, m0, n0, K, c, smv);

    const int t = threadIdx.x, lane = t & 31, wid = t >> 5;
    const int gid = lane >> 2, tig = lane & 3, wm = wid >> 2, wn = wid & 3;
    #pragma unroll
    for (int i = 0; i < 4; i++) {
        #pragma unroll
        for (int rr = 0; rr < 2; rr++) {
            int m = m0 + wm*64 + i*16 + gid + rr*8;
            #pragma unroll
            for (int j = 0; j < 4; j++) {
                float v0 = c[i][j][rr*2 + 0], v1 = c[i][j][rr*2 + 1];
                float x = 0.5f * v0 * (1.f + erff(v0 * 0.70710678118654752f)) * v1;
                float xo = __shfl_xor_sync(0xffffffffu, x, 1);
                if (!(tig & 1)) {
                    size_t o = (size_t)m*INTER2 + (n0>>2) + wn*8 + j*2 + (tig>>1);
                    xhi[o] = packh(x, xo);
                }
            }
        }
    }
}

// ---------------------------------------------------------------------------
// Fused flash attention (proven R14): scores + bias + softmax + PV.
// V s-major; PV B-fragments via ldmatrix.trans.
// smem: [0,8K) Q | [8K,72K) K -> P | [72K,136K) V
// ---------------------------------------------------------------------------
__global__ __launch_bounds__(256, 1)
void attn_fused(const uint32_t* __restrict__ qhi,
                const float* __restrict__ mask, const float* __restrict__ kb,
                uint32_t* __restrict__ athi)
{
    extern __shared__ char smv[];
    __shared__ float mask_s[SS], kb_s[SS];
    __shared__ float redmax[2][64], redsum[2][64];

    const int bh = blockIdx.y, b = bh / NH, hh = bh % NH;
    const int m0 = blockIdx.x * 64;
    const int t = threadIdx.x, lane = t & 31, wid = t >> 5;
    const int gid = lane >> 2, tig = lane & 3;
    const int wm = wid >> 1, wn = wid & 1;

    const uint32_t sb = (uint32_t)__cvta_generic_to_shared(smv);
    const uint32_t sQH = sb, sKH = sb + 8192, sV = sb + 73728, sP = sKH;

    const uint32_t* Qh = qhi + (size_t)b*SS*QKVN2 + hh*32;
    const uint32_t* Kh = Qh + HID2;
    const uint32_t* Vh = Qh + 2*HID2;

    #pragma unroll
    for (int it = 0; it < 2; it++) {
        int idx = t + it*256, row = idx >> 3, chunk = (idx >> 2) & 1, ch = idx & 3;
        size_t go = (size_t)(m0 + row)*QKVN2 + chunk*16 + ch*4;
        cp16s(sQH + chunk*4096 + swz(row, ch), Qh + go);
    }
    #pragma unroll
    for (int it = 0; it < 8; it++) {
        int idx = t + it*256, row = idx >> 2, chunk = (idx >> 1) & 1, ch2 = (idx & 1) * 2;
        size_t go = (size_t)row*QKVN2 + chunk*16 + ch2*4;
        cp16s(sKH + chunk*32768 + swz(row, ch2), Kh + go);
        cp16s(sKH + chunk*32768 + swz(row, ch2+1), Kh + go + 4);
    }
    #pragma unroll
    for (int it = 0; it < 8; it++) {
        int idx = t + it*256, row = idx >> 2, chunk = (idx >> 1) & 1, ch2 = (idx & 1) * 2;
        size_t go = (size_t)row*QKVN2 + chunk*16 + ch2*4;
        cp16s(sV + chunk*32768 + swz(row, ch2), Vh + go);
        cp16s(sV + chunk*32768 + swz(row, ch2+1), Vh + go + 4);
    }
    {
        uint32_t ms = (uint32_t)__cvta_generic_to_shared(mask_s);
        uint32_t ks = (uint32_t)__cvta_generic_to_shared(kb_s);
        if (t < 128) cp16s(ms + t*16, mask + b*SS + t*4);
        else         cp16s(ks + (t-128)*16, kb + hh*SS + (t-128)*4);
    }
    asm volatile("cp.async.commit_group;");
    asm volatile("cp.async.wait_group 0;");
    __syncthreads();

    // ---- scores ----
    float c[32][4] = {};
    #pragma unroll
    for (int s4 = 0; s4 < 4; s4++) {
        int chunk = s4 >> 1, ss_ = s4 & 1;
        int arow = wm*16 + (lane & 15);
        int ach = ss_*2 + (lane >> 4);
        uint32_t ah[4];
        ldsm4(ah, sQH + chunk*4096 + swz(arow, ach));
        int browb = wn*256 + (lane & 7) + ((lane >> 4) << 3);
        int bch = ss_*2 + ((lane >> 3) & 1);
        #pragma unroll
        for (int jp = 0; jp < 16; jp++) {
            uint32_t bh_[4];
            ldsm4(bh_, sKH + chunk*32768 + swz(browb + jp*16, bch));
            mma16(c[2*jp],   ah, bh_);
            mma16(c[2*jp+1], ah, bh_ + 2);
        }
    }

    // ---- bias + softmax ----
    const int mrow0 = m0 + wm*16 + gid, mrow1 = mrow0 + 8;
    float mx0 = -1e30f, mx1 = -1e30f;
    #pragma unroll
    for (int j = 0; j < 32; j++) {
        int n = wn*256 + j*8 + tig*2;
        #pragma unroll
        for (int u = 0; u < 2; u++) {
            int nn = n + u;
            float badd = (mask_s[nn] - 1.f) * 10000.f;
            int r0 = mrow0 > nn ? mrow0 - nn : nn - mrow0;
            int r1 = mrow1 > nn ? mrow1 - nn : nn - mrow1;
            c[j][u]   = c[j][u]   * 0.125f + kb_s[r0] + badd;
            c[j][2+u] = c[j][2+u] * 0.125f + kb_s[r1] + badd;
            mx0 = fmaxf(mx0, c[j][u]);
            mx1 = fmaxf(mx1, c[j][2+u]);
        }
    }
    mx0 = fmaxf(mx0, __shfl_xor_sync(~0u, mx0, 1));
    mx0 = fmaxf(mx0, __shfl_xor_sync(~0u, mx0, 2));
    mx1 = fmaxf(mx1, __shfl_xor_sync(~0u, mx1, 1));
    mx1 = fmaxf(mx1, __shfl_xor_sync(~0u, mx1, 2));
    if (tig == 0) { redmax[wn][wm*16+gid] = mx0; redmax[wn][wm*16+gid+8] = mx1; }
    __syncthreads();
    mx0 = fmaxf(redmax[0][wm*16+gid],   redmax[1][wm*16+gid]);
    mx1 = fmaxf(redmax[0][wm*16+gid+8], redmax[1][wm*16+gid+8]);

    float s0 = 0.f, s1 = 0.f;
    #pragma unroll
    for (int j = 0; j < 32; j++) {
        #pragma unroll
        for (int u = 0; u < 2; u++) {
            c[j][u]   = __expf(c[j][u]   - mx0); s0 += c[j][u];
            c[j][2+u] = __expf(c[j][2+u] - mx1); s1 += c[j][2+u];
        }
    }
    s0 += __shfl_xor_sync(~0u, s0, 1); s0 += __shfl_xor_sync(~0u, s0, 2);
    s1 += __shfl_xor_sync(~0u, s1, 1); s1 += __shfl_xor_sync(~0u, s1, 2);
    if (tig == 0) { redsum[wn][wm*16+gid] = s0; redsum[wn][wm*16+gid+8] = s1; }
    __syncthreads();
    float inv0 = 1.f / (redsum[0][wm*16+gid]   + redsum[1][wm*16+gid]);
    float inv1 = 1.f / (redsum[0][wm*16+gid+8] + redsum[1][wm*16+gid+8]);

    // ---- write P into smem over K region ----
    const int lr0 = wm*16 + gid, lr1 = lr0 + 8;
    #pragma unroll
    for (int j = 0; j < 32; j++) {
        int col = wn*256 + j*8 + tig*2;
        int cc = col & 31;
        uint32_t base = sP + (col >> 5) * 4096 + ((cc >> 1) & 3) * 4;
        sts32(base + swz(lr0, cc >> 3), packh(c[j][0]*inv0, c[j][1]*inv0));
        sts32(base + swz(lr1, cc >> 3), packh(c[j][2]*inv1, c[j][3]*inv1));
    }
    __syncthreads();

    // ---- PV: B-fragments from s-major V via ldmatrix.trans ----
    float c2[4][4] = {};
    const int g = lane >> 3, L = lane & 7;
    #pragma unroll
    for (int kc = 0; kc < 16; kc++) {
        #pragma unroll
        for (int s2 = 0; s2 < 2; s2++) {
            int arow = wm*16 + (lane & 15);
            int ach = s2*2 + (lane >> 4);
            uint32_t ah[4];
            ldsm4(ah, sP + kc*4096 + swz(arow, ach));
            int srow = kc*32 + s2*16 + ((g & 1) << 3) + L;
            #pragma unroll
            for (int jp = 0; jp < 2; jp++) {
                int d_base = wn*32 + jp*16;
                int chunk_d = d_base >> 5;
                int ch_d = ((d_base & 31) >> 3) + (g >> 1);
                uint32_t rg[4];
                ldsm4t(rg, sV + chunk_d*32768 + swz(srow, ch_d));
                mma16(c2[jp*2],   ah, rg);
                mma16(c2[jp*2+1], ah, rg + 2);
            }
        }
    }

    #pragma unroll
    for (int rr = 0; rr < 2; rr++) {
        int m = m0 + wm*16 + gid + rr*8;
        #pragma unroll
        for (int j = 0; j < 4; j++) {
            int n = wn*32 + j*8 + tig*2;
            size_t o = (size_t)(b*SS + m)*HID2 + hh*32 + (n>>1);
            athi[o] = packh(c2[j][rr*2 + 0], c2[j][rr*2 + 1]);
        }
    }
}

// ---------------------------------------------------------------------------
// Elementwise / small kernels (R14 proven versions)
// ---------------------------------------------------------------------------
__global__ void cvt_kernel(const float* __restrict__ in, uint32_t* __restrict__ hi) {
    size_t p = ((size_t)blockIdx.x * blockDim.x + threadIdx.x) * 4;
    float4 a = *(const float4*)(in + 2*p);
    float4 b = *(const float4*)(in + 2*p + 4);
    *(uint4*)(hi + p) = make_uint4(packh(a.x,a.y), packh(a.z,a.w),
                                   packh(b.x,b.y), packh(b.z,b.w));
}

__global__ void glu_cvt_kernel(const float* __restrict__ gluw, uint32_t* __restrict__ hi) {
    int idx = blockIdx.x * 256 + threadIdx.x;
    int R = idx / 96;
    int g4 = idx % 96;
    int l = R / (2*INTER), r = R % (2*INTER);
    int srcrow = (r & 1) ? (INTER + (r >> 1)) : (r >> 1);
    const float* src = gluw + ((size_t)l*2*INTER + srcrow)*HID + g4*8;
    float4 a = *(const float4*)(src);
    float4 b = *(const float4*)(src + 4);
    size_t p = (size_t)R*HID2 + g4*4;
    *(uint4*)(hi + p) = make_uint4(packh(a.x,a.y), packh(a.z,a.w),
                                   packh(b.x,b.y), packh(b.z,b.w));
}

__global__ void mask_init_kernel(const float* __restrict__ hs, const float* __restrict__ mask,
                                 uint32_t* __restrict__ hhi) {
    size_t p = (size_t)blockIdx.x * 256 + threadIdx.x;
    size_t row = p / HID2;
    float m = mask[row];
    hhi[p] = packh(hs[2*p] * m, hs[2*p+1] * m);
}

__global__ void kerple_kernel(const float* __restrict__ r1, const float* __restrict__ r2,
                              const float* __restrict__ r3, float* __restrict__ kb) {
    int rel = threadIdx.x;
    int l = blockIdx.x;
    for (int h = 0; h < NH; h++) {
        float c1 = fmaxf(r1[l*NH + h], 1e-7f);
        float c2 = fmaxf(r2[l*NH + h], 1e-7f);
        float c3 = fmaxf(r3[l*NH + h], 1e-7f);
        float v = 0.f;
        if (rel > 0) v = -c1 * log1pf(c2 * powf((float)rel, c3));
        kb[(l*NH + h)*SS + rel] = v;
    }
}

// ---------------------------------------------------------------------------
// LayerNorm over 768 from packed-fp16 input; packed-fp16 out (+opt fp32).
// ---------------------------------------------------------------------------
__global__ __launch_bounds__(384)
void ln_kernel(const uint32_t* __restrict__ yhi, const float* __restrict__ gma,
               const float* __restrict__ bta, const float* __restrict__ mask,
               float* __restrict__ outF, uint32_t* __restrict__ ohi) {
    const int row = blockIdx.x;
    const int t = threadIdx.x, w = t >> 5, ln = t & 31;
    float ax, ay;
    unpackh(yhi[(size_t)row*HID2 + t], ax, ay);

    __shared__ float red[12];
    float s = ax + ay;
    #pragma unroll
    for (int o = 16; o; o >>= 1) s += __shfl_xor_sync(~0u, s, o);
    if (ln == 0) red[w] = s;
    __syncthreads();
    float tot = 0.f;
    #pragma unroll
    for (int i = 0; i < 12; i++) tot += red[i];
    float mu = tot * (1.f / HID);
    __syncthreads();

    float d0 = ax - mu, d1 = ay - mu;
    float ss = d0*d0 + d1*d1;
    #pragma unroll
    for (int o = 16; o; o >>= 1) ss += __shfl_xor_sync(~0u, ss, o);
    if (ln == 0) red[w] = ss;
    __syncthreads();
    float vtot = 0.f;
    #pragma unroll
    for (int i = 0; i < 12; i++) vtot += red[i];
    float inv = rsqrtf(vtot * (1.f / HID) + 1e-12f);
    float mm = mask[row];

    float o0 = (d0 * inv * gma[2*t]   + bta[2*t])   * mm;
    float o1 = (d1 * inv * gma[2*t+1] + bta[2*t+1]) * mm;
    if (outF) {
        outF[(size_t)row*HID + 2*t]   = o0;
        outF[(size_t)row*HID + 2*t+1] = o1;
    }
    ohi[(size_t)row*HID2 + t] = packh(o0, o1);
}

// ---------------------------------------------------------------------------
// Launch
// ---------------------------------------------------------------------------
extern "C" void kernel_launch(void* const* d_in, const int* in_sizes, int n_in,
                              void* d_out, int out_size) {
    const float* hs     = (const float*)d_in[0];
    const float* mask   = (const float*)d_in[1];
    const float* Wqkv_w = (const float*)d_in[2];
    const float* Wqkv_b = (const float*)d_in[3];
    const float* aow    = (const float*)d_in[4];
    const float* aob    = (const float*)d_in[5];
    const float* ln1g   = (const float*)d_in[6];
    const float* ln1b   = (const float*)d_in[7];
    const float* gluw   = (const float*)d_in[8];
    const float* wow    = (const float*)d_in[9];
    const float* wob    = (const float*)d_in[10];
    const float* ln2g   = (const float*)d_in[11];
    const float* ln2b   = (const float*)d_in[12];
    const float* r1     = (const float*)d_in[13];
    const float* r2     = (const float*)d_in[14];
    const float* r3     = (const float*)d_in[15];

    float *kb;
    uint32_t *h_hi,*y_hi,*qkv_hi,*at_hi,*ao_hi,*x_hi;
    uint32_t *wqkv_hi,*wao_hi,*wglu_hi,*wwo_hi;
    cudaGetSymbolAddress((void**)&kb, g_kb);
    cudaGetSymbolAddress((void**)&h_hi, g_h_hi);
    cudaGetSymbolAddress((void**)&y_hi, g_y_hi);
    cudaGetSymbolAddress((void**)&qkv_hi, g_qkv_hi);
    cudaGetSymbolAddress((void**)&at_hi, g_at_hi);
    cudaGetSymbolAddress((void**)&ao_hi, g_ao_hi);
    cudaGetSymbolAddress((void**)&x_hi, g_x_hi);
    cudaGetSymbolAddress((void**)&wqkv_hi, g_wqkv_hi);
    cudaGetSymbolAddress((void**)&wao_hi, g_wao_hi);
    cudaGetSymbolAddress((void**)&wglu_hi, g_wglu_hi);
    cudaGetSymbolAddress((void**)&wwo_hi, g_wwo_hi);

    cudaFuncSetAttribute(gemm_h,    cudaFuncAttributeMaxDynamicSharedMemorySize, 49152);
    cudaFuncSetAttribute(gemm_h64,  cudaFuncAttributeMaxDynamicSharedMemorySize, 36864);
    cudaFuncSetAttribute(gemm_glu,  cudaFuncAttributeMaxDynamicSharedMemorySize, 49152);
    cudaFuncSetAttribute(attn_fused, cudaFuncAttributeMaxDynamicSharedMemorySize, 139264);

    // weight converts + kerple (once per call)
    cvt_kernel<<<LAY*QKVN*HID/8/256, 256>>>(Wqkv_w, wqkv_hi);
    cvt_kernel<<<LAY*HID*HID/8/256, 256>>>(aow, wao_hi);
    glu_cvt_kernel<<<(int)((size_t)LAY*2*INTER*96/256), 256>>>(gluw, wglu_hi);
    cvt_kernel<<<(int)((size_t)LAY*HID*INTER/8/256), 256>>>(wow, wwo_hi);
    kerple_kernel<<<LAY, SS>>>(r1, r2, r3, kb);

    mask_init_kernel<<<TOK*HID2/256, 256>>>(hs, mask, h_hi);

    for (int l = 0; l < LAY; l++) {
        // qkv = (h @ Wqkv^T + b) * mask
        gemm_h<<<dim3(QKVN/128, TOK/128), 256, 49152>>>(
            h_hi, wqkv_hi + (size_t)l*QKVN*HID/2,
            Wqkv_b + (size_t)l*QKVN, nullptr, mask, qkv_hi,
            TOK, QKVN, HID);

        attn_fused<<<dim3(SS/64, BNH), 256, 139264>>>(
            qkv_hi, mask, kb + (size_t)l*NH*SS, at_hi);

        // y = attn @ attn_out_w^T + b + h   (N=768 -> 64-wide tiles)
        gemm_h64<<<dim3(HID/64, TOK/128), 256, 36864>>>(
            at_hi, wao_hi + (size_t)l*HID*HID/2,
            aob + (size_t)l*HID, h_hi, nullptr, y_hi,
            TOK, HID, HID);
        ln_kernel<<<TOK, 384>>>(y_hi, ln1g + (size_t)l*HID, ln1b + (size_t)l*HID, mask,
                                nullptr, ao_hi);

        // GLU + gelu*mul fused
        gemm_glu<<<dim3(2*INTER/128, TOK/128), 256, 49152>>>(
            ao_hi, wglu_hi + (size_t)l*2*INTER*HID/2, x_hi, HID);

        // y = x @ wo_w^T + b + ao           (N=768 -> 64-wide tiles)
        gemm_h64<<<dim3(HID/64, TOK/128), 256, 36864>>>(
            x_hi, wwo_hi + (size_t)l*HID*INTER/2,
            wob + (size_t)l*HID, ao_hi, nullptr, y_hi,
            TOK, HID, INTER);

        float* outF = (l == LAY-1) ? (float*)d_out : nullptr;
        ln_kernel<<<TOK, 384>>>(y_hi, ln2g + (size_t)l*HID, ln2b + (size_t)l*HID, mask,
                                outF, h_hi);
    }
}

// round 17
// speedup vs baseline: 1.1375x; 1.1375x over previous
#include <cuda_runtime.h>
#include <cuda_fp16.h>
#include <math.h>
#include <stdint.h>

#define BB 8
#define SS 512
#define HID 768
#define NH 12
#define DHD 64
#define INTER 3072
#define LAY 4
#define TOK (BB*SS)
#define QKVN (3*HID)
#define BNH (BB*NH)
#define HID2 (HID/2)
#define QKVN2 (QKVN/2)
#define INTER2 (INTER/2)
#define SS2 (SS/2)

// ---------------------------------------------------------------------------
// Scratch (all packed-fp16x2)
// ---------------------------------------------------------------------------
__device__ float g_kb [LAY*NH*SS];

__device__ uint32_t g_h_hi [TOK*HID2];
__device__ uint32_t g_y_hi [TOK*HID2];
__device__ uint32_t g_qkv_hi[TOK*QKVN2];
__device__ uint32_t g_at_hi[TOK*HID2];
__device__ uint32_t g_ao_hi[TOK*HID2];
__device__ uint32_t g_x_hi [(size_t)TOK*INTER2];

__device__ uint32_t g_wqkv_hi[LAY*QKVN*HID/2];
__device__ uint32_t g_wao_hi [LAY*HID*HID/2];
__device__ uint32_t g_wglu_hi[(size_t)LAY*2*INTER*HID/2];
__device__ uint32_t g_wwo_hi [(size_t)LAY*HID*INTER/2];

// ---------------------------------------------------------------------------
// Helpers
// ---------------------------------------------------------------------------
__device__ __forceinline__ uint32_t packh(float f0, float f1) {
    __half h0 = __float2half_rn(f0), h1 = __float2half_rn(f1);
    return ((uint32_t)__half_as_ushort(h1) << 16) | (uint32_t)__half_as_ushort(h0);
}

__device__ __forceinline__ void unpackh(uint32_t hi, float& f0, float& f1) {
    f0 = __half2float(__ushort_as_half((unsigned short)(hi & 0xffff)));
    f1 = __half2float(__ushort_as_half((unsigned short)(hi >> 16)));
}

__device__ __forceinline__ void mma16(float* c, const uint32_t* a, const uint32_t* b) {
    asm volatile(
        "mma.sync.aligned.m16n8k16.row.col.f32.f16.f16.f32 "
        "{%0,%1,%2,%3}, {%4,%5,%6,%7}, {%8,%9}, {%0,%1,%2,%3};"
        : "+f"(c[0]), "+f"(c[1]), "+f"(c[2]), "+f"(c[3])
        : "r"(a[0]), "r"(a[1]), "r"(a[2]), "r"(a[3]), "r"(b[0]), "r"(b[1]));
}

__device__ __forceinline__ void ldsm4(uint32_t* r, uint32_t saddr) {
    asm volatile("ldmatrix.sync.aligned.m8n8.x4.shared.b16 {%0,%1,%2,%3}, [%4];"
        : "=r"(r[0]), "=r"(r[1]), "=r"(r[2]), "=r"(r[3]) : "r"(saddr));
}

__device__ __forceinline__ void ldsm4t(uint32_t* r, uint32_t saddr) {
    asm volatile("ldmatrix.sync.aligned.m8n8.x4.trans.shared.b16 {%0,%1,%2,%3}, [%4];"
        : "=r"(r[0]), "=r"(r[1]), "=r"(r[2]), "=r"(r[3]) : "r"(saddr));
}

__device__ __forceinline__ void cp16s(uint32_t saddr, const void* g) {
    asm volatile("cp.async.ca.shared.global [%0], [%1], 16;" :: "r"(saddr), "l"(g));
}

__device__ __forceinline__ void sts32(uint32_t saddr, uint32_t v) {
    asm volatile("st.shared.u32 [%0], %1;" :: "r"(saddr), "r"(v) : "memory");
}

__device__ __forceinline__ int swz(int row, int ch) {
    return row * 64 + ((ch ^ ((row >> 1) & 3)) << 4);
}

// ---------------------------------------------------------------------------
// FP16 single-pass mainloop (proven R14: BK=32, 3-stage cp.async)
// ---------------------------------------------------------------------------
template<int IT, int JT, int WM, int WN, int BROWS>
__device__ __forceinline__ void mainloop(
    const uint32_t* __restrict__ Ahi, int lda2,
    const uint32_t* __restrict__ Bhi, int ldb2,
    int m0, int n0, int K, float (*c)[JT][4], char* smptr)
{
    constexpr int ASZ = 128 * 64;
    constexpr int BSZ = BROWS * 64;
    constexpr int STG = ASZ + BSZ;
    constexpr int BITER = (BROWS * 4) / 256;
    const int t = threadIdx.x, lane = t & 31, wid = t >> 5;
    const int wm = wid / WN, wn = wid % WN;
    const uint32_t sbase = (uint32_t)__cvta_generic_to_shared(smptr);
    const int KT = K >> 5;

    auto prefetch = [&](int st, int k0) {
        int kc = k0 >> 1;
        uint32_t s0 = sbase + st * STG;
        #pragma unroll
        for (int it2 = 0; it2 < 2; it2++) {
            int idx = t + it2 * 256; int row = idx >> 2, ch = idx & 3;
            cp16s(s0 + swz(row, ch), Ahi + (size_t)(m0 + row) * lda2 + kc + ch * 4);
        }
        #pragma unroll
        for (int it2 = 0; it2 < BITER; it2++) {
            int idx = t + it2 * 256; int row = idx >> 2, ch = idx & 3;
            cp16s(s0 + ASZ + swz(row, ch), Bhi + (size_t)(n0 + row) * ldb2 + kc + ch * 4);
        }
        asm volatile("cp.async.commit_group;");
    };

    prefetch(0, 0);
    if (KT > 1) prefetch(1, 32);

    for (int kt = 0; kt < KT; kt++) {
        int st = kt % 3;
        if (kt + 2 < KT)      { prefetch((kt + 2) % 3, (kt + 2) * 32);
                                asm volatile("cp.async.wait_group 2;"); }
        else if (kt + 1 < KT) { asm volatile("cp.async.wait_group 1;"); }
        else                  { asm volatile("cp.async.wait_group 0;"); }
        __syncthreads();

        uint32_t aH = sbase + st * STG;
        uint32_t bH = aH + ASZ;

        #pragma unroll
        for (int s = 0; s < 2; s++) {
            const int arow = wm * IT * 16 + (lane & 15);
            const int ach  = s * 2 + (lane >> 4);
            const int brow = wn * JT * 8 + (lane & 7) + ((lane >> 4) << 3);
            const int bch  = s * 2 + ((lane >> 3) & 1);

            uint32_t ah[IT][4], bh_[JT][2];
            #pragma unroll
            for (int i = 0; i < IT; i++)
                ldsm4(ah[i], aH + swz(arow + i * 16, ach));
            #pragma unroll
            for (int jp = 0; jp < JT / 2; jp++) {
                uint32_t rg[4];
                ldsm4(rg, bH + swz(brow + jp * 16, bch));
                bh_[jp*2][0] = rg[0]; bh_[jp*2][1] = rg[1];
                bh_[jp*2+1][0] = rg[2]; bh_[jp*2+1][1] = rg[3];
            }
            #pragma unroll
            for (int i = 0; i < IT; i++)
                #pragma unroll
                for (int j = 0; j < JT; j++)
                    mma16(c[i][j], ah[i], bh_[j]);
        }
        __syncthreads();
    }
}

// ---------------------------------------------------------------------------
// Generic GEMM (128x128 tile, 2 CTAs/SM) — proven R14
// ---------------------------------------------------------------------------
__global__ __launch_bounds__(256, 2)
void gemm_h(const uint32_t* __restrict__ Ahi,
            const uint32_t* __restrict__ Whi,
            const float* __restrict__ bias, const uint32_t* __restrict__ resHi,
            const float* __restrict__ mask,
            uint32_t* __restrict__ outHi, int M, int N, int K)
{
    extern __shared__ char smv[];
    float c[4][4][4] = {};
    const int m0 = blockIdx.y * 128, n0 = blockIdx.x * 128;
    mainloop<4,4,2,4,128>(Ahi, K/2, Whi, K/2, m0, n0, K, c, smv);

    const int t = threadIdx.x, lane = t & 31, wid = t >> 5;
    const int gid = lane >> 2, tig = lane & 3, wm = wid >> 2, wn = wid & 3;
    const int N2 = N >> 1;
    #pragma unroll
    for (int i = 0; i < 4; i++) {
        #pragma unroll
        for (int rr = 0; rr < 2; rr++) {
            int m = m0 + wm*64 + i*16 + gid + rr*8;
            float mm = mask ? mask[m] : 1.f;
            #pragma unroll
            for (int j = 0; j < 4; j++) {
                int n = n0 + wn*32 + j*8 + tig*2;
                float v0 = c[i][j][rr*2 + 0], v1 = c[i][j][rr*2 + 1];
                if (bias) { v0 += bias[n]; v1 += bias[n+1]; }
                if (resHi) {
                    float r0, r1; unpackh(resHi[(size_t)m*N2 + (n>>1)], r0, r1);
                    v0 += r0; v1 += r1;
                }
                outHi[(size_t)m*N2 + (n>>1)] = packh(v0 * mm, v1 * mm);
            }
        }
    }
}

// ---------------------------------------------------------------------------
// GLU GEMM (128x128): interleaved weights; epilogue x = gelu(gate)*up
// ---------------------------------------------------------------------------
__global__ __launch_bounds__(256, 2)
void gemm_glu(const uint32_t* __restrict__ Ahi,
              const uint32_t* __restrict__ Whi,
              uint32_t* __restrict__ xhi, int K)
{
    extern __shared__ char smv[];
    float c[4][4][4] = {};
    const int m0 = blockIdx.y * 128, n0 = blockIdx.x * 128;
    mainloop<4,4,2,4,128>(Ahi, K/2, Whi, K/2, m0, n0, K, c, smv);

    const int t = threadIdx.x, lane = t & 31, wid = t >> 5;
    const int gid = lane >> 2, tig = lane & 3, wm = wid >> 2, wn = wid & 3;
    #pragma unroll
    for (int i = 0; i < 4; i++) {
        #pragma unroll
        for (int rr = 0; rr < 2; rr++) {
            int m = m0 + wm*64 + i*16 + gid + rr*8;
            #pragma unroll
            for (int j = 0; j < 4; j++) {
                float v0 = c[i][j][rr*2 + 0], v1 = c[i][j][rr*2 + 1];
                float x = 0.5f * v0 * (1.f + erff(v0 * 0.70710678118654752f)) * v1;
                float xo = __shfl_xor_sync(0xffffffffu, x, 1);
                if (!(tig & 1)) {
                    size_t o = (size_t)m*INTER2 + (n0>>2) + wn*8 + j*2 + (tig>>1);
                    xhi[o] = packh(x, xo);
                }
            }
        }
    }
}

// ---------------------------------------------------------------------------
// Fused flash attention: 2 q-tiles (128 rows) per block; K/V loaded once.
// smem: [0,16K) Q (2 tiles) | [16K,80K) K | [80K,144K) V | [144K,208K) P
// Per-tile body identical to R14 (bit-identical output).
// ---------------------------------------------------------------------------
__global__ __launch_bounds__(256, 1)
void attn_fused(const uint32_t* __restrict__ qhi,
                const float* __restrict__ mask, const float* __restrict__ kb,
                uint32_t* __restrict__ athi)
{
    extern __shared__ char smv[];
    __shared__ float mask_s[SS], kb_s[SS];
    __shared__ float redmax[2][64], redsum[2][64];

    const int bh = blockIdx.y, b = bh / NH, hh = bh % NH;
    const int m0 = blockIdx.x * 128;
    const int t = threadIdx.x, lane = t & 31, wid = t >> 5;
    const int gid = lane >> 2, tig = lane & 3;
    const int wm = wid >> 1, wn = wid & 1;

    const uint32_t sb = (uint32_t)__cvta_generic_to_shared(smv);
    const uint32_t sQH = sb, sKH = sb + 16384, sV = sb + 81920, sP = sb + 147456;

    const uint32_t* Qh = qhi + (size_t)b*SS*QKVN2 + hh*32;
    const uint32_t* Kh = Qh + HID2;
    const uint32_t* Vh = Qh + 2*HID2;

    // Q: 128 rows (2 tiles of 64), each tile 2 chunks of 32 elems
    #pragma unroll
    for (int qt = 0; qt < 2; qt++) {
        #pragma unroll
        for (int it = 0; it < 2; it++) {
            int idx = t + it*256, row = idx >> 3, chunk = (idx >> 2) & 1, ch = idx & 3;
            size_t go = (size_t)(m0 + qt*64 + row)*QKVN2 + chunk*16 + ch*4;
            cp16s(sQH + qt*8192 + chunk*4096 + swz(row, ch), Qh + go);
        }
    }
    // K: 512 rows x 64 d (2 d-half chunks)
    #pragma unroll
    for (int it = 0; it < 8; it++) {
        int idx = t + it*256, row = idx >> 2, chunk = (idx >> 1) & 1, ch2 = (idx & 1) * 2;
        size_t go = (size_t)row*QKVN2 + chunk*16 + ch2*4;
        cp16s(sKH + chunk*32768 + swz(row, ch2), Kh + go);
        cp16s(sKH + chunk*32768 + swz(row, ch2+1), Kh + go + 4);
    }
    // V: same layout as K (s-major)
    #pragma unroll
    for (int it = 0; it < 8; it++) {
        int idx = t + it*256, row = idx >> 2, chunk = (idx >> 1) & 1, ch2 = (idx & 1) * 2;
        size_t go = (size_t)row*QKVN2 + chunk*16 + ch2*4;
        cp16s(sV + chunk*32768 + swz(row, ch2), Vh + go);
        cp16s(sV + chunk*32768 + swz(row, ch2+1), Vh + go + 4);
    }
    {
        uint32_t ms = (uint32_t)__cvta_generic_to_shared(mask_s);
        uint32_t ks = (uint32_t)__cvta_generic_to_shared(kb_s);
        if (t < 128) cp16s(ms + t*16, mask + b*SS + t*4);
        else         cp16s(ks + (t-128)*16, kb + hh*SS + (t-128)*4);
    }
    asm volatile("cp.async.commit_group;");
    asm volatile("cp.async.wait_group 0;");
    __syncthreads();

    for (int qt = 0; qt < 2; qt++) {
        if (qt) __syncthreads();   // P/red-array reuse: prior PV reads done
        const int mq = m0 + qt*64;
        const uint32_t sQ = sQH + qt*8192;

        // ---- scores ----
        float c[32][4] = {};
        #pragma unroll
        for (int s4 = 0; s4 < 4; s4++) {
            int chunk = s4 >> 1, ss_ = s4 & 1;
            int arow = wm*16 + (lane & 15);
            int ach = ss_*2 + (lane >> 4);
            uint32_t ah[4];
            ldsm4(ah, sQ + chunk*4096 + swz(arow, ach));
            int browb = wn*256 + (lane & 7) + ((lane >> 4) << 3);
            int bch = ss_*2 + ((lane >> 3) & 1);
            #pragma unroll
            for (int jp = 0; jp < 16; jp++) {
                uint32_t bh_[4];
                ldsm4(bh_, sKH + chunk*32768 + swz(browb + jp*16, bch));
                mma16(c[2*jp],   ah, bh_);
                mma16(c[2*jp+1], ah, bh_ + 2);
            }
        }

        // ---- bias + softmax ----
        const int mrow0 = mq + wm*16 + gid, mrow1 = mrow0 + 8;
        float mx0 = -1e30f, mx1 = -1e30f;
        #pragma unroll
        for (int j = 0; j < 32; j++) {
            int n = wn*256 + j*8 + tig*2;
            #pragma unroll
            for (int u = 0; u < 2; u++) {
                int nn = n + u;
                float badd = (mask_s[nn] - 1.f) * 10000.f;
                int r0 = mrow0 > nn ? mrow0 - nn : nn - mrow0;
                int r1 = mrow1 > nn ? mrow1 - nn : nn - mrow1;
                c[j][u]   = c[j][u]   * 0.125f + kb_s[r0] + badd;
                c[j][2+u] = c[j][2+u] * 0.125f + kb_s[r1] + badd;
                mx0 = fmaxf(mx0, c[j][u]);
                mx1 = fmaxf(mx1, c[j][2+u]);
            }
        }
        mx0 = fmaxf(mx0, __shfl_xor_sync(~0u, mx0, 1));
        mx0 = fmaxf(mx0, __shfl_xor_sync(~0u, mx0, 2));
        mx1 = fmaxf(mx1, __shfl_xor_sync(~0u, mx1, 1));
        mx1 = fmaxf(mx1, __shfl_xor_sync(~0u, mx1, 2));
        if (tig == 0) { redmax[wn][wm*16+gid] = mx0; redmax[wn][wm*16+gid+8] = mx1; }
        __syncthreads();
        mx0 = fmaxf(redmax[0][wm*16+gid],   redmax[1][wm*16+gid]);
        mx1 = fmaxf(redmax[0][wm*16+gid+8], redmax[1][wm*16+gid+8]);

        float s0 = 0.f, s1 = 0.f;
        #pragma unroll
        for (int j = 0; j < 32; j++) {
            #pragma unroll
            for (int u = 0; u < 2; u++) {
                c[j][u]   = __expf(c[j][u]   - mx0); s0 += c[j][u];
                c[j][2+u] = __expf(c[j][2+u] - mx1); s1 += c[j][2+u];
            }
        }
        s0 += __shfl_xor_sync(~0u, s0, 1); s0 += __shfl_xor_sync(~0u, s0, 2);
        s1 += __shfl_xor_sync(~0u, s1, 1); s1 += __shfl_xor_sync(~0u, s1, 2);
        if (tig == 0) { redsum[wn][wm*16+gid] = s0; redsum[wn][wm*16+gid+8] = s1; }
        __syncthreads();
        float inv0 = 1.f / (redsum[0][wm*16+gid]   + redsum[1][wm*16+gid]);
        float inv1 = 1.f / (redsum[0][wm*16+gid+8] + redsum[1][wm*16+gid+8]);

        // ---- write P into smem (separate region; K preserved) ----
        const int lr0 = wm*16 + gid, lr1 = lr0 + 8;
        #pragma unroll
        for (int j = 0; j < 32; j++) {
            int col = wn*256 + j*8 + tig*2;
            int cc = col & 31;
            uint32_t base = sP + (col >> 5) * 4096 + ((cc >> 1) & 3) * 4;
            sts32(base + swz(lr0, cc >> 3), packh(c[j][0]*inv0, c[j][1]*inv0));
            sts32(base + swz(lr1, cc >> 3), packh(c[j][2]*inv1, c[j][3]*inv1));
        }
        __syncthreads();

        // ---- PV: B-fragments from s-major V via ldmatrix.trans ----
        float c2[4][4] = {};
        const int g = lane >> 3, L = lane & 7;
        #pragma unroll
        for (int kc = 0; kc < 16; kc++) {
            #pragma unroll
            for (int s2 = 0; s2 < 2; s2++) {
                int arow = wm*16 + (lane & 15);
                int ach = s2*2 + (lane >> 4);
                uint32_t ah[4];
                ldsm4(ah, sP + kc*4096 + swz(arow, ach));
                int srow = kc*32 + s2*16 + ((g & 1) << 3) + L;
                #pragma unroll
                for (int jp = 0; jp < 2; jp++) {
                    int d_base = wn*32 + jp*16;
                    int chunk_d = d_base >> 5;
                    int ch_d = ((d_base & 31) >> 3) + (g >> 1);
                    uint32_t rg[4];
                    ldsm4t(rg, sV + chunk_d*32768 + swz(srow, ch_d));
                    mma16(c2[jp*2],   ah, rg);
                    mma16(c2[jp*2+1], ah, rg + 2);
                }
            }
        }

        #pragma unroll
        for (int rr = 0; rr < 2; rr++) {
            int m = mq + wm*16 + gid + rr*8;
            #pragma unroll
            for (int j = 0; j < 4; j++) {
                int n = wn*32 + j*8 + tig*2;
                size_t o = (size_t)(b*SS + m)*HID2 + hh*32 + (n>>1);
                athi[o] = packh(c2[j][rr*2 + 0], c2[j][rr*2 + 1]);
            }
        }
    }
}

// ---------------------------------------------------------------------------
// Elementwise / small kernels (R14 proven versions)
// ---------------------------------------------------------------------------
__global__ void cvt_kernel(const float* __restrict__ in, uint32_t* __restrict__ hi) {
    size_t p = ((size_t)blockIdx.x * blockDim.x + threadIdx.x) * 4;
    float4 a = *(const float4*)(in + 2*p);
    float4 b = *(const float4*)(in + 2*p + 4);
    *(uint4*)(hi + p) = make_uint4(packh(a.x,a.y), packh(a.z,a.w),
                                   packh(b.x,b.y), packh(b.z,b.w));
}

__global__ void glu_cvt_kernel(const float* __restrict__ gluw, uint32_t* __restrict__ hi) {
    int idx = blockIdx.x * 256 + threadIdx.x;
    int R = idx / 96;
    int g4 = idx % 96;
    int l = R / (2*INTER), r = R % (2*INTER);
    int srcrow = (r & 1) ? (INTER + (r >> 1)) : (r >> 1);
    const float* src = gluw + ((size_t)l*2*INTER + srcrow)*HID + g4*8;
    float4 a = *(const float4*)(src);
    float4 b = *(const float4*)(src + 4);
    size_t p = (size_t)R*HID2 + g4*4;
    *(uint4*)(hi + p) = make_uint4(packh(a.x,a.y), packh(a.z,a.w),
                                   packh(b.x,b.y), packh(b.z,b.w));
}

__global__ void mask_init_kernel(const float* __restrict__ hs, const float* __restrict__ mask,
                                 uint32_t* __restrict__ hhi) {
    size_t p = (size_t)blockIdx.x * 256 + threadIdx.x;
    size_t row = p / HID2;
    float m = mask[row];
    hhi[p] = packh(hs[2*p] * m, hs[2*p+1] * m);
}

__global__ void kerple_kernel(const float* __restrict__ r1, const float* __restrict__ r2,
                              const float* __restrict__ r3, float* __restrict__ kb) {
    int rel = threadIdx.x;
    int l = blockIdx.x;
    for (int h = 0; h < NH; h++) {
        float c1 = fmaxf(r1[l*NH + h], 1e-7f);
        float c2 = fmaxf(r2[l*NH + h], 1e-7f);
        float c3 = fmaxf(r3[l*NH + h], 1e-7f);
        float v = 0.f;
        if (rel > 0) v = -c1 * log1pf(c2 * powf((float)rel, c3));
        kb[(l*NH + h)*SS + rel] = v;
    }
}

// ---------------------------------------------------------------------------
// LayerNorm over 768 from packed-fp16 input; packed-fp16 out (+opt fp32).
// ---------------------------------------------------------------------------
__global__ __launch_bounds__(384)
void ln_kernel(const uint32_t* __restrict__ yhi, const float* __restrict__ gma,
               const float* __restrict__ bta, const float* __restrict__ mask,
               float* __restrict__ outF, uint32_t* __restrict__ ohi) {
    const int row = blockIdx.x;
    const int t = threadIdx.x, w = t >> 5, ln = t & 31;
    float ax, ay;
    unpackh(yhi[(size_t)row*HID2 + t], ax, ay);

    __shared__ float red[12];
    float s = ax + ay;
    #pragma unroll
    for (int o = 16; o; o >>= 1) s += __shfl_xor_sync(~0u, s, o);
    if (ln == 0) red[w] = s;
    __syncthreads();
    float tot = 0.f;
    #pragma unroll
    for (int i = 0; i < 12; i++) tot += red[i];
    float mu = tot * (1.f / HID);
    __syncthreads();

    float d0 = ax - mu, d1 = ay - mu;
    float ss = d0*d0 + d1*d1;
    #pragma unroll
    for (int o = 16; o; o >>= 1) ss += __shfl_xor_sync(~0u, ss, o);
    if (ln == 0) red[w] = ss;
    __syncthreads();
    float vtot = 0.f;
    #pragma unroll
    for (int i = 0; i < 12; i++) vtot += red[i];
    float inv = rsqrtf(vtot * (1.f / HID) + 1e-12f);
    float mm = mask[row];

    float o0 = (d0 * inv * gma[2*t]   + bta[2*t])   * mm;
    float o1 = (d1 * inv * gma[2*t+1] + bta[2*t+1]) * mm;
    if (outF) {
        outF[(size_t)row*HID + 2*t]   = o0;
        outF[(size_t)row*HID + 2*t+1] = o1;
    }
    ohi[(size_t)row*HID2 + t] = packh(o0, o1);
}

// ---------------------------------------------------------------------------
// Launch
// ---------------------------------------------------------------------------
extern "C" void kernel_launch(void* const* d_in, const int* in_sizes, int n_in,
                              void* d_out, int out_size) {
    const float* hs     = (const float*)d_in[0];
    const float* mask   = (const float*)d_in[1];
    const float* Wqkv_w = (const float*)d_in[2];
    const float* Wqkv_b = (const float*)d_in[3];
    const float* aow    = (const float*)d_in[4];
    const float* aob    = (const float*)d_in[5];
    const float* ln1g   = (const float*)d_in[6];
    const float* ln1b   = (const float*)d_in[7];
    const float* gluw   = (const float*)d_in[8];
    const float* wow    = (const float*)d_in[9];
    const float* wob    = (const float*)d_in[10];
    const float* ln2g   = (const float*)d_in[11];
    const float* ln2b   = (const float*)d_in[12];
    const float* r1     = (const float*)d_in[13];
    const float* r2     = (const float*)d_in[14];
    const float* r3     = (const float*)d_in[15];

    float *kb;
    uint32_t *h_hi,*y_hi,*qkv_hi,*at_hi,*ao_hi,*x_hi;
    uint32_t *wqkv_hi,*wao_hi,*wglu_hi,*wwo_hi;
    cudaGetSymbolAddress((void**)&kb, g_kb);
    cudaGetSymbolAddress((void**)&h_hi, g_h_hi);
    cudaGetSymbolAddress((void**)&y_hi, g_y_hi);
    cudaGetSymbolAddress((void**)&qkv_hi, g_qkv_hi);
    cudaGetSymbolAddress((void**)&at_hi, g_at_hi);
    cudaGetSymbolAddress((void**)&ao_hi, g_ao_hi);
    cudaGetSymbolAddress((void**)&x_hi, g_x_hi);
    cudaGetSymbolAddress((void**)&wqkv_hi, g_wqkv_hi);
    cudaGetSymbolAddress((void**)&wao_hi, g_wao_hi);
    cudaGetSymbolAddress((void**)&wglu_hi, g_wglu_hi);
    cudaGetSymbolAddress((void**)&wwo_hi, g_wwo_hi);

    cudaFuncSetAttribute(gemm_h,    cudaFuncAttributeMaxDynamicSharedMemorySize, 49152);
    cudaFuncSetAttribute(gemm_glu,  cudaFuncAttributeMaxDynamicSharedMemorySize, 49152);
    cudaFuncSetAttribute(attn_fused, cudaFuncAttributeMaxDynamicSharedMemorySize, 212992);

    // weight converts + kerple (once per call)
    cvt_kernel<<<LAY*QKVN*HID/8/256, 256>>>(Wqkv_w, wqkv_hi);
    cvt_kernel<<<LAY*HID*HID/8/256, 256>>>(aow, wao_hi);
    glu_cvt_kernel<<<(int)((size_t)LAY*2*INTER*96/256), 256>>>(gluw, wglu_hi);
    cvt_kernel<<<(int)((size_t)LAY*HID*INTER/8/256), 256>>>(wow, wwo_hi);
    kerple_kernel<<<LAY, SS>>>(r1, r2, r3, kb);

    mask_init_kernel<<<TOK*HID2/256, 256>>>(hs, mask, h_hi);

    for (int l = 0; l < LAY; l++) {
        // qkv = (h @ Wqkv^T + b) * mask
        gemm_h<<<dim3(QKVN/128, TOK/128), 256, 49152>>>(
            h_hi, wqkv_hi + (size_t)l*QKVN*HID/2,
            Wqkv_b + (size_t)l*QKVN, nullptr, mask, qkv_hi,
            TOK, QKVN, HID);

        attn_fused<<<dim3(SS/128, BNH), 256, 212992>>>(
            qkv_hi, mask, kb + (size_t)l*NH*SS, at_hi);

        // y = attn @ attn_out_w^T + b + h
        gemm_h<<<dim3(HID/128, TOK/128), 256, 49152>>>(
            at_hi, wao_hi + (size_t)l*HID*HID/2,
            aob + (size_t)l*HID, h_hi, nullptr, y_hi,
            TOK, HID, HID);
        ln_kernel<<<TOK, 384>>>(y_hi, ln1g + (size_t)l*HID, ln1b + (size_t)l*HID, mask,
                                nullptr, ao_hi);

        // GLU + gelu*mul fused
        gemm_glu<<<dim3(2*INTER/128, TOK/128), 256, 49152>>>(
            ao_hi, wglu_hi + (size_t)l*2*INTER*HID/2, x_hi, HID);

        // y = x @ wo_w^T + b + ao
        gemm_h<<<dim3(HID/128, TOK/128), 256, 49152>>>(
            x_hi, wwo_hi + (size_t)l*HID*INTER/2,
            wob + (size_t)l*HID, ao_hi, nullptr, y_hi,
            TOK, HID, INTER);

        float* outF = (l == LAY-1) ? (float*)d_out : nullptr;
        ln_kernel<<<TOK, 384>>>(y_hi, ln2g + (size_t)l*HID, ln2b + (size_t)l*HID, mask,
                                outF, h_hi);
    }
}